// round 4
// baseline (speedup 1.0000x reference)
#include <cuda_runtime.h>
#include <cstdint>
#include <cstddef>

// Problem constants
#define BATCH 8
#define SEQ   2048
#define DIM   1024
#define NEGV  (-1e9f)

// GEMM tiling
#define BK  16
#define LDT 132   // padded smem row stride (floats); multiple of 4 for float4 ops

// Scratch (static device globals are allowed; runtime allocs are not)
__device__ float g_Q [(size_t)BATCH * SEQ * DIM];
__device__ float g_K [(size_t)BATCH * SEQ * DIM];
__device__ float g_V [(size_t)BATCH * SEQ * DIM];
__device__ float g_Y1[(size_t)BATCH * SEQ * DIM];
__device__ unsigned char g_mask[(size_t)BATCH * SEQ];

// ---------------------------------------------------------------------------
// Mask decode: the reference mask is numpy bool; the harness may marshal it
// as packed bytes, int32, or float32. mask[0] is guaranteed true (lengths >=
// N/2), so the first 32-bit word discriminates:
//   0x01010101 -> packed u8 bool bytes
//   0x00000001 -> int32
//   0x3F800000 -> float32
// ---------------------------------------------------------------------------
__global__ void mask_decode_kernel(const void* __restrict__ raw,
                                   unsigned char* __restrict__ outm, int n) {
    int i = blockIdx.x * blockDim.x + threadIdx.x;
    if (i >= n) return;
    unsigned int w0 = *(const unsigned int*)raw;
    unsigned char m;
    if (w0 == 1u) {                       // int32
        m = (((const int*)raw)[i] != 0) ? 1 : 0;
    } else if (w0 == 0x3F800000u) {       // float32
        m = (((const float*)raw)[i] != 0.0f) ? 1 : 0;
    } else {                              // packed bytes (bool/uint8)
        m = (((const unsigned char*)raw)[i] != 0) ? 1 : 0;
    }
    outm[i] = m;
}

// ---------------------------------------------------------------------------
// packed f32x2 helpers (FFMA2 is only reachable via PTX fma.rn.f32x2)
// ---------------------------------------------------------------------------
__device__ __forceinline__ unsigned long long pack2(float a) {
    unsigned long long r;
    unsigned int u = __float_as_uint(a);
    asm("mov.b64 %0, {%1, %1};" : "=l"(r) : "r"(u));
    return r;
}

__device__ __forceinline__ void ffma2(unsigned long long& c,
                                      unsigned long long a,
                                      unsigned long long b) {
    asm("fma.rn.f32x2 %0, %1, %2, %0;" : "+l"(c) : "l"(a), "l"(b));
}

union U64F2 { unsigned long long u; float2 f; };
union F4U2  { float4 f; unsigned long long u[2]; };

// ---------------------------------------------------------------------------
// Shared-memory tile loaders
// ---------------------------------------------------------------------------
// NT loader: G is [rows, Kd] row-major; tile rows r0..r0+127, cols k0..k0+15.
// Stores transposed: S[k][r].
__device__ __forceinline__ void load_nt(const float* __restrict__ G, int ld,
                                        int r0, int k0,
                                        float (*S)[LDT], int tid) {
    int lr = tid >> 2;           // 0..63
    int lc = (tid & 3) * 4;      // 0,4,8,12
#pragma unroll
    for (int p = 0; p < 2; ++p) {
        int r = lr + p * 64;
        float4 v = *(const float4*)(G + (size_t)(r0 + r) * ld + k0 + lc);
        S[lc + 0][r] = v.x;
        S[lc + 1][r] = v.y;
        S[lc + 2][r] = v.z;
        S[lc + 3][r] = v.w;
    }
}

// TN loader: G is [Kdim, cols] row-major; tile k-rows k0..k0+15, cols c0..c0+127.
// Direct copy: S[k][c].
__device__ __forceinline__ void load_tn(const float* __restrict__ G, int ld,
                                        int c0, int k0,
                                        float (*S)[LDT], int tid) {
    int lr = tid >> 5;           // 0..7
    int lc = (tid & 31) * 4;     // 0..124
#pragma unroll
    for (int p = 0; p < 2; ++p) {
        int kk = lr + p * 8;
        *(float4*)&S[kk][lc] =
            *(const float4*)(G + (size_t)(k0 + kk) * ld + c0 + lc);
    }
}

// ---------------------------------------------------------------------------
// Per-tile FFMA2 core: 8x8 accum per thread, packed along the n dimension
// ---------------------------------------------------------------------------
__device__ __forceinline__ void mma_tile(const float (*As)[LDT],
                                         const float (*Bs)[LDT],
                                         unsigned long long acc[8][4],
                                         int arow, int bcol) {
#pragma unroll
    for (int k = 0; k < BK; ++k) {
        float4 a0 = *(const float4*)&As[k][arow];
        float4 a1 = *(const float4*)&As[k][arow + 4];
        F4U2 ub0, ub1;
        ub0.f = *(const float4*)&Bs[k][bcol];
        ub1.f = *(const float4*)&Bs[k][bcol + 4];
        unsigned long long bb[4] = { ub0.u[0], ub0.u[1], ub1.u[0], ub1.u[1] };
        float av[8] = { a0.x, a0.y, a0.z, a0.w, a1.x, a1.y, a1.z, a1.w };
#pragma unroll
        for (int i = 0; i < 8; ++i) {
            unsigned long long a2 = pack2(av[i]);
#pragma unroll
            for (int j = 0; j < 4; ++j) ffma2(acc[i][j], a2, bb[j]);
        }
    }
}

__device__ __forceinline__ void acc_zero(unsigned long long acc[8][4]) {
#pragma unroll
    for (int i = 0; i < 8; ++i)
#pragma unroll
        for (int j = 0; j < 4; ++j) acc[i][j] = 0ull;
}

// ---------------------------------------------------------------------------
// Kernel: C[M,N] = alpha * A[M,K] @ B[N,K]^T    (both K-contiguous; "NT")
// Used for Q/K/V projections and the final Wo projection.
// ---------------------------------------------------------------------------
__global__ __launch_bounds__(256)
void gemm_nt_kernel(const float* __restrict__ A, const float* __restrict__ Bm,
                    float* __restrict__ C, int M, int Nn, int Kd, float alpha) {
    __shared__ float As[BK][LDT];
    __shared__ float Bs[BK][LDT];
    int tid = threadIdx.x;
    int m0 = blockIdx.y * 128, n0 = blockIdx.x * 128;
    int arow = (tid >> 4) * 8, bcol = (tid & 15) * 8;

    unsigned long long acc[8][4];
    acc_zero(acc);

    for (int k0 = 0; k0 < Kd; k0 += BK) {
        load_nt(A,  Kd, m0, k0, As, tid);
        load_nt(Bm, Kd, n0, k0, Bs, tid);
        __syncthreads();
        mma_tile(As, Bs, acc, arow, bcol);
        __syncthreads();
    }

#pragma unroll
    for (int i = 0; i < 8; ++i) {
        float o[8];
#pragma unroll
        for (int j = 0; j < 4; ++j) {
            U64F2 t; t.u = acc[i][j];
            o[2 * j]     = t.f.x * alpha;
            o[2 * j + 1] = t.f.y * alpha;
        }
        float* cp = C + (size_t)(m0 + arow + i) * Nn + n0 + bcol;
        *(float4*)(cp)     = make_float4(o[0], o[1], o[2], o[3]);
        *(float4*)(cp + 4) = make_float4(o[4], o[5], o[6], o[7]);
    }
}

// ---------------------------------------------------------------------------
// Kernel: logits[b] = Q[b] @ K[b]^T with padding mask -> NEGV
// Writes directly into the att_weights region of d_out.
// ---------------------------------------------------------------------------
__global__ __launch_bounds__(256)
void logits_kernel(const float* __restrict__ Qg, const float* __restrict__ Kg,
                   const unsigned char* __restrict__ mk_all,
                   float* __restrict__ att) {
    __shared__ float As[BK][LDT];
    __shared__ float Bs[BK][LDT];
    int z = blockIdx.z;
    const float* A  = Qg + (size_t)z * SEQ * DIM;
    const float* Bm = Kg + (size_t)z * SEQ * DIM;
    float* C = att + (size_t)z * SEQ * SEQ;
    const unsigned char* mk = mk_all + (size_t)z * SEQ;

    int tid = threadIdx.x;
    int m0 = blockIdx.y * 128, n0 = blockIdx.x * 128;
    int arow = (tid >> 4) * 8, bcol = (tid & 15) * 8;

    unsigned long long acc[8][4];
    acc_zero(acc);

    for (int k0 = 0; k0 < DIM; k0 += BK) {
        load_nt(A,  DIM, m0, k0, As, tid);
        load_nt(Bm, DIM, n0, k0, Bs, tid);
        __syncthreads();
        mma_tile(As, Bs, acc, arow, bcol);
        __syncthreads();
    }

    bool mj[8];
#pragma unroll
    for (int j = 0; j < 8; ++j) mj[j] = (mk[n0 + bcol + j] != 0);

#pragma unroll
    for (int i = 0; i < 8; ++i) {
        bool mi = (mk[m0 + arow + i] != 0);
        float o[8];
#pragma unroll
        for (int j = 0; j < 4; ++j) {
            U64F2 t; t.u = acc[i][j];
            o[2 * j]     = t.f.x;
            o[2 * j + 1] = t.f.y;
        }
#pragma unroll
        for (int j = 0; j < 8; ++j)
            o[j] = (mi && mj[j]) ? o[j] : NEGV;
        float* cp = C + (size_t)(m0 + arow + i) * SEQ + n0 + bcol;
        *(float4*)(cp)     = make_float4(o[0], o[1], o[2], o[3]);
        *(float4*)(cp + 4) = make_float4(o[4], o[5], o[6], o[7]);
    }
}

// ---------------------------------------------------------------------------
// Row softmax over SEQ=2048, in place. One block per row.
// ---------------------------------------------------------------------------
__global__ __launch_bounds__(256)
void softmax_kernel(float* __restrict__ att) {
    __shared__ float red[256];
    float* p = att + (size_t)blockIdx.x * SEQ;
    int tid = threadIdx.x;

    float v[8];
    float mx = -3.4e38f;
#pragma unroll
    for (int i = 0; i < 8; ++i) {
        v[i] = p[tid + 256 * i];
        mx = fmaxf(mx, v[i]);
    }
    red[tid] = mx;
    __syncthreads();
    for (int s = 128; s > 0; s >>= 1) {
        if (tid < s) red[tid] = fmaxf(red[tid], red[tid + s]);
        __syncthreads();
    }
    mx = red[0];
    __syncthreads();

    float sum = 0.f;
#pragma unroll
    for (int i = 0; i < 8; ++i) {
        v[i] = __expf(v[i] - mx);
        sum += v[i];
    }
    red[tid] = sum;
    __syncthreads();
    for (int s = 128; s > 0; s >>= 1) {
        if (tid < s) red[tid] += red[tid + s];
        __syncthreads();
    }
    float inv = 1.0f / red[0];
#pragma unroll
    for (int i = 0; i < 8; ++i) p[tid + 256 * i] = v[i] * inv;
}

// ---------------------------------------------------------------------------
// Kernel: Y1[b,i,d] = sum_j att[b,j,i] * V[b,j,d]   ("TN": A^T @ V per batch)
// ---------------------------------------------------------------------------
__global__ __launch_bounds__(256)
void atv_kernel(const float* __restrict__ att, const float* __restrict__ Vg,
                float* __restrict__ Y1) {
    __shared__ float As[BK][LDT];
    __shared__ float Bs[BK][LDT];
    int z = blockIdx.z;
    const float* A  = att + (size_t)z * SEQ * SEQ;  // [j, i]
    const float* Bv = Vg  + (size_t)z * SEQ * DIM;  // [j, d]
    float* C = Y1 + (size_t)z * SEQ * DIM;

    int tid = threadIdx.x;
    int i0 = blockIdx.y * 128, n0 = blockIdx.x * 128;
    int arow = (tid >> 4) * 8, bcol = (tid & 15) * 8;

    unsigned long long acc[8][4];
    acc_zero(acc);

    for (int k0 = 0; k0 < SEQ; k0 += BK) {
        load_tn(A,  SEQ, i0, k0, As, tid);
        load_tn(Bv, DIM, n0, k0, Bs, tid);
        __syncthreads();
        mma_tile(As, Bs, acc, arow, bcol);
        __syncthreads();
    }

#pragma unroll
    for (int i = 0; i < 8; ++i) {
        float o[8];
#pragma unroll
        for (int j = 0; j < 4; ++j) {
            U64F2 t; t.u = acc[i][j];
            o[2 * j]     = t.f.x;
            o[2 * j + 1] = t.f.y;
        }
        float* cp = C + (size_t)(i0 + arow + i) * DIM + n0 + bcol;
        *(float4*)(cp)     = make_float4(o[0], o[1], o[2], o[3]);
        *(float4*)(cp + 4) = make_float4(o[4], o[5], o[6], o[7]);
    }
}

// ---------------------------------------------------------------------------
// Launch
// ---------------------------------------------------------------------------
extern "C" void kernel_launch(void* const* d_in, const int* in_sizes, int n_in,
                              void* d_out, int out_size) {
    const float* x       = (const float*)d_in[0];
    const void*  mraw    = (const void*)d_in[1];
    const float* Wq      = (const float*)d_in[2];
    const float* Wk      = (const float*)d_in[3];
    const float* Wv      = (const float*)d_in[4];
    const float* Wo      = (const float*)d_in[5];

    float* y_out = (float*)d_out;
    float* att   = (float*)d_out + (size_t)BATCH * SEQ * DIM;

    float *Q, *K_, *V, *Y1;
    unsigned char* mk;
    cudaGetSymbolAddress((void**)&Q,  g_Q);
    cudaGetSymbolAddress((void**)&K_, g_K);
    cudaGetSymbolAddress((void**)&V,  g_V);
    cudaGetSymbolAddress((void**)&Y1, g_Y1);
    cudaGetSymbolAddress((void**)&mk, g_mask);

    const int MROWS = BATCH * SEQ;  // 16384

    // canonicalize mask dtype -> uint8
    mask_decode_kernel<<<(BATCH * SEQ + 255) / 256, 256>>>(mraw, mk, BATCH * SEQ);

    // Q/K/V projections (Q pre-scaled by 0.06)
    gemm_nt_kernel<<<dim3(DIM / 128, MROWS / 128), 256>>>(x, Wq, Q,  MROWS, DIM, DIM, 0.06f);
    gemm_nt_kernel<<<dim3(DIM / 128, MROWS / 128), 256>>>(x, Wk, K_, MROWS, DIM, DIM, 1.0f);
    gemm_nt_kernel<<<dim3(DIM / 128, MROWS / 128), 256>>>(x, Wv, V,  MROWS, DIM, DIM, 1.0f);

    // masked logits -> att region of d_out
    logits_kernel<<<dim3(SEQ / 128, SEQ / 128, BATCH), 256>>>(Q, K_, mk, att);

    // in-place row softmax
    softmax_kernel<<<BATCH * SEQ, 256>>>(att);

    // Y1 = att^T @ V per batch
    atv_kernel<<<dim3(DIM / 128, SEQ / 128, BATCH), 256>>>(att, V, Y1);

    // y = Y1 @ Wo^T
    gemm_nt_kernel<<<dim3(DIM / 128, MROWS / 128), 256>>>(Y1, Wo, y_out, MROWS, DIM, DIM, 1.0f);
}